// round 13
// baseline (speedup 1.0000x reference)
#include <cuda_runtime.h>
#include <cuda_fp16.h>
#include <math.h>
#include <stdint.h>

#define BATCH  8192
#define LATENT 256
#define CD     128
#define UDIM   32
#define NY     50
#define NTH    256

// ---------------- scratch (static device globals; no allocation) ----------------
__device__ __half g_A0 [BATCH * 320];
__device__ __half g_W0 [256 * 320];
__device__ __half g_W1 [256 * 256];
__device__ __half g_W2 [256 * 256];
__device__ __half g_Wao[256 * 256];
__device__ float  g_Bao[256];
__device__ __half g_Wbt[8192 * 256];     // rows 0-4095 btr, 4096-8191 bti
__device__ float  g_Bbt[8192];
__device__ __half g_Wct[12800 * 256];    // row y*256+part*128+c  <- (ctr|cti)[y*128+c]
__device__ float  g_Bct[12800];
__device__ __half g_Wdtw[1600 * 256];
__device__ __half g_x1[BATCH * LATENT];
__device__ __half g_x2[BATCH * LATENT];
__device__ __half g_hz[BATCH * LATENT];
__device__ float g_ao[BATCH * LATENT];
__device__ float g_zincr[BATCH * 256];   // cols 0-127 real incr, 128-255 imag incr
__device__ float g_ytc[2 * BATCH * NY];  // [0]=Re partial, [1]=Im-weight partial
__device__ float g_ytd[BATCH * NY];

// ---------------- PTX helpers ----------------
__device__ __forceinline__ void ldsm4(uint32_t& a0, uint32_t& a1, uint32_t& a2, uint32_t& a3,
                                      uint32_t addr) {
    asm volatile("ldmatrix.sync.aligned.m8n8.x4.shared.b16 {%0,%1,%2,%3}, [%4];"
                 : "=r"(a0), "=r"(a1), "=r"(a2), "=r"(a3) : "r"(addr));
}
__device__ __forceinline__ void mma_f16(float* c,
                                        uint32_t a0, uint32_t a1, uint32_t a2, uint32_t a3,
                                        uint32_t b0, uint32_t b1) {
    asm volatile(
        "mma.sync.aligned.m16n8k16.row.col.f32.f16.f16.f32 "
        "{%0,%1,%2,%3},{%4,%5,%6,%7},{%8,%9},{%0,%1,%2,%3};"
        : "+f"(c[0]), "+f"(c[1]), "+f"(c[2]), "+f"(c[3])
        : "r"(a0), "r"(a1), "r"(a2), "r"(a3), "r"(b0), "r"(b1));
}
__device__ __forceinline__ void cp16(uint32_t dst, const void* src, int sz) {
    asm volatile("cp.async.cg.shared.global [%0], [%1], 16, %2;"
                 :: "r"(dst), "l"(src), "r"(sz));
}

// ---------------- prep: convert all GEMM operands to fp16 ----------------
#define E_A0  (BATCH * 320)
#define E_W0  (E_A0  + 256 * 320)
#define E_W1  (E_W0  + 65536)
#define E_W2  (E_W1  + 65536)
#define E_WAO (E_W2  + 65536)
#define E_BAO (E_WAO + 256)
#define E_WBT (E_BAO + 8192 * 256)
#define E_BBT (E_WBT + 8192)
#define E_WCT (E_BBT + 12800 * 256)
#define E_BCT (E_WCT + 12800)
#define E_DTW (E_BCT + 1600 * 256)

__global__ void prep_kernel(const float* __restrict__ zt, const float* __restrict__ dt,
                            const float* __restrict__ ut,
                            const float* __restrict__ sw0, const float* __restrict__ sw1,
                            const float* __restrict__ sw2,
                            const float* __restrict__ aw, const float* __restrict__ ab,
                            const float* __restrict__ ow, const float* __restrict__ ob,
                            const float* __restrict__ btr, const float* __restrict__ btr_b,
                            const float* __restrict__ bti, const float* __restrict__ bti_b,
                            const float* __restrict__ ctr, const float* __restrict__ ctr_b,
                            const float* __restrict__ cti, const float* __restrict__ cti_b,
                            const float* __restrict__ dtw)
{
    for (int idx = blockIdx.x * blockDim.x + threadIdx.x; idx < E_DTW;
         idx += gridDim.x * blockDim.x) {
        if (idx < E_A0) {
            int m = idx / 320, c = idx % 320;
            float v = 0.f;
            if (c < 256)       v = zt[m * 256 + c];
            else if (c < 288)  v = ut[m * UDIM + (c - 256)];
            else if (c == 288) v = dt[m];
            g_A0[idx] = __float2half(v);
        } else if (idx < E_W0) {
            int j = idx - E_A0;
            int r = j / 320, c = j % 320;
            g_W0[j] = __float2half((c < 289) ? sw0[r * 289 + c] : 0.f);
        } else if (idx < E_W1) {
            int j = idx - E_W0;  g_W1[j] = __float2half(sw1[j]);
        } else if (idx < E_W2) {
            int j = idx - E_W1;  g_W2[j] = __float2half(sw2[j]);
        } else if (idx < E_WAO) {
            int j = idx - E_W2;
            g_Wao[j] = __float2half((j < 128 * 256) ? aw[j] : ow[j - 128 * 256]);
        } else if (idx < E_BAO) {
            int j = idx - E_WAO;
            g_Bao[j] = (j < 128) ? ab[j] : ob[j - 128];
        } else if (idx < E_WBT) {
            int j = idx - E_BAO;
            g_Wbt[j] = __float2half((j < 4096 * 256) ? btr[j] : bti[j - 4096 * 256]);
        } else if (idx < E_BBT) {
            int j = idx - E_WBT;
            g_Bbt[j] = (j < 4096) ? btr_b[j] : bti_b[j - 4096];
        } else if (idx < E_WCT) {
            int j = idx - E_BBT;
            int r = j >> 8, k = j & 255;
            int y = r >> 8, part = (r >> 7) & 1, c = r & 127;
            int srow = (y * 128 + c) * 256 + k;
            g_Wct[j] = __float2half(part == 0 ? ctr[srow] : cti[srow]);
        } else if (idx < E_BCT) {
            int r = idx - E_WCT;
            int y = r >> 8, part = (r >> 7) & 1, c = r & 127;
            g_Bct[r] = part == 0 ? ctr_b[y * 128 + c] : cti_b[y * 128 + c];
        } else {
            int j = idx - E_BCT; g_Wdtw[j] = __float2half(dtw[j]);
        }
    }
}

// ---------------------------------------------------------------------------
// fp16 m16n8k16 fused GEMM, 256 threads. Templated M-tile (MT) and K-chunks (NC).
// CTA tile (MT*32) x 128, BK=64, 3-stage cp.async, unrolled mainloop,
// double-buffered B fragments. 8 warps as 2(m) x 4(n); warp tile (MT*16) x 32.
//   MODE 1: BN(eval)+ReLU -> half out, ldc=256
//   MODE 2: +bias -> half out (OUTH=1) or float out (OUTH=0), ldc=256
//   MODE 3: +bias, contract 32-col u-group/warp with ut*dt, ldc by caller
//   MODE 4: +bias, contract tile's 128 cols with zv[part] (y=by>>1), out ytc
//   MODE 5: MODE 3 with group bounds (Dt), ldc=NY
// ---------------------------------------------------------------------------
template <int MODE, int OUTH, int MT, int NC>
__global__ __launch_bounds__(NTH, 2)
void gemm_hc(const __half* __restrict__ A,
             const __half* __restrict__ W, int N,
             const float* __restrict__ bias,
             const float* __restrict__ p0,   // ut (3/5) | zv base (4)
             const float* __restrict__ p1,   // dt (3/5)
             const float* __restrict__ p2,   // bn gamma (1)
             const float* __restrict__ p3,   // bn beta  (1)
             void* __restrict__ Cout, int ldc)
{
    constexpr int K = NC * 64;
    constexpr int MTILE = MT * 32;                 // 64 or 128
    constexpr int STAGE_BYTES = (MTILE + 128) * 128;
    constexpr int STGW = STAGE_BYTES / 4;
    constexpr int CTRLW = 3 * STGW;

    extern __shared__ float sm[];
    float* sbias = sm + CTRLW;
    float* sg    = sbias + 128;
    float* sbe   = sg + 128;
    float* red   = sbe + 128;                      // MTILE*4 floats (MODE 4)

    const int tid  = threadIdx.x;
    const int lane = tid & 31;
    const int warp = tid >> 5;
    const int m0 = blockIdx.x * MTILE;
    const int n0 = blockIdx.y * 128;
    const int wm = warp >> 2;           // 0..1  (MTILE/2 rows each)
    const int wn = warp & 3;            // 0..3  (32 cols each)
    const int gq = lane >> 2;
    const int tq = lane & 3;
    const uint32_t smu = (uint32_t)__cvta_generic_to_shared(sm);

    if (tid < 128) {
        int n = n0 + tid;
        sbias[tid] = (n < N) ? bias[n] : 0.f;
        if (MODE == 1) {
            sg[tid]  = p2[n] * rsqrtf(1.f + 1e-5f);
            sbe[tid] = p3[n];
        }
    }

    float acc[MT][4][4];
#pragma unroll
    for (int i = 0; i < MT; i++)
#pragma unroll
        for (int j = 0; j < 4; j++)
#pragma unroll
            for (int r = 0; r < 4; r++) acc[i][j][r] = 0.f;

    // A ldmatrix lane constants
    const int row_off = lane & 15;
    const int hi = lane >> 4;
    uint32_t abyte[MT]; int arx[MT];
#pragma unroll
    for (int mt = 0; mt < MT; mt++) {
        int r = wm * (MT * 16) + mt * 16 + row_off;
        abyte[mt] = smu + (uint32_t)(r * 128);
        arx[mt] = r & 7;
    }
    // B ldmatrix lane constants (2 x ldsm.x4 per k16-step, same bits as scalar path)
    const int brx = lane & 7;
    const int gpx = (lane >> 3) & 1;
    const uint32_t bb1 = smu + (uint32_t)((MTILE + wn * 32 + (lane >> 4) * 8 + brx) * 128);
    const uint32_t bb2 = bb1 + 16 * 128;

    auto issue = [&](int kc, int s) {
        const int tot = (MTILE + 128) * 8;
        for (int i = tid; i < tot; i += NTH) {
            int r = i >> 3, g16 = i & 7;
            uint32_t dst; const __half* src; int sz = 16;
            if (r < MTILE) {
                dst = smu + (uint32_t)(s * STAGE_BYTES + r * 128 + ((g16 ^ (r & 7)) << 4));
                src = A + (size_t)(m0 + r) * K + kc * 64 + g16 * 8;
            } else {
                int rb = r - MTILE;
                dst = smu + (uint32_t)(s * STAGE_BYTES + MTILE * 128 + rb * 128 + ((g16 ^ (rb & 7)) << 4));
                int n = n0 + rb;
                if (n < N) src = W + (size_t)n * K + kc * 64 + g16 * 8;
                else { src = W; sz = 0; }
            }
            cp16(dst, src, sz);
        }
        asm volatile("cp.async.commit_group;" ::: "memory");
    };

    auto loadB = [&](int ks, uint32_t* f0, uint32_t* f1, uint32_t sa) {
        const uint32_t gx = (uint32_t)(((2 * ks + gpx) ^ brx) << 4);
        ldsm4(f0[0], f1[0], f0[1], f1[1], bb1 + sa + gx);
        ldsm4(f0[2], f1[2], f0[3], f1[3], bb2 + sa + gx);
    };

    auto compute = [&](int s) {
        const uint32_t sa = (uint32_t)(s * STAGE_BYTES);
        uint32_t bf0[2][4], bf1[2][4];
        loadB(0, bf0[0], bf1[0], sa);
#pragma unroll
        for (int ks = 0; ks < 4; ks++) {           // 4 x k16 per 64-k chunk
            const int cur = ks & 1;
            if (ks < 3) loadB(ks + 1, bf0[cur ^ 1], bf1[cur ^ 1], sa);
            const int ga = 2 * ks + hi;
#pragma unroll
            for (int mt = 0; mt < MT; mt++) {
                uint32_t a0, a1, a2, a3;
                ldsm4(a0, a1, a2, a3, abyte[mt] + sa + (uint32_t)((ga ^ arx[mt]) << 4));
#pragma unroll
                for (int nt = 0; nt < 4; nt++)
                    mma_f16(acc[mt][nt], a0, a1, a2, a3, bf0[cur][nt], bf1[cur][nt]);
            }
        }
    };

    issue(0, 0);
    issue(1, 1);
#pragma unroll
    for (int kc = 0; kc < NC; kc++) {
        asm volatile("cp.async.wait_group 1;" ::: "memory");
        __syncthreads();
        if (kc + 2 < NC) issue(kc + 2, (kc + 2) % 3);
        else asm volatile("cp.async.commit_group;" ::: "memory");
        compute(kc % 3);
    }

    // ---------------- epilogues ----------------
    // acc r=h*2+p -> m = m0+wm*(MT*16)+mt*16+gq+h*8 ; col nl = wn*32+nt*8+tq*2+p
    if (MODE <= 2) {
#pragma unroll
        for (int nt = 0; nt < 4; nt++)
#pragma unroll
            for (int p = 0; p < 2; p++) {
                int nl = wn * 32 + nt * 8 + tq * 2 + p;
                int n = n0 + nl;
                float bi = sbias[nl];
                float gg = (MODE == 1) ? sg[nl] : 0.f;
                float bb = (MODE == 1) ? sbe[nl] : 0.f;
#pragma unroll
                for (int mt = 0; mt < MT; mt++)
#pragma unroll
                    for (int h = 0; h < 2; h++) {
                        int m = m0 + wm * (MT * 16) + mt * 16 + gq + h * 8;
                        float v = acc[mt][nt][h * 2 + p] + bi;
                        if (MODE == 1) v = fmaxf(v * gg + bb, 0.f);
                        if (OUTH) ((__half*)Cout)[(size_t)m * ldc + n] = __float2half(v);
                        else      ((float*)Cout)[(size_t)m * ldc + n] = v;
                    }
            }
    } else if (MODE == 3 || MODE == 5) {
        const int gcol = blockIdx.y * 4 + wn;
        const bool gvalid = (MODE == 3) || (gcol < NY);
        float* Cf = (float*)Cout;
#pragma unroll
        for (int mt = 0; mt < MT; mt++)
#pragma unroll
            for (int h = 0; h < 2; h++) {
                int m = m0 + wm * (MT * 16) + mt * 16 + gq + h * 8;
                float s = 0.f;
#pragma unroll
                for (int nt = 0; nt < 4; nt++)
#pragma unroll
                    for (int p = 0; p < 2; p++) {
                        int u = nt * 8 + tq * 2 + p;
                        s += (acc[mt][nt][h * 2 + p] + sbias[wn * 32 + u])
                             * p0[(size_t)m * UDIM + u];
                    }
                s += __shfl_xor_sync(0xffffffffu, s, 1);
                s += __shfl_xor_sync(0xffffffffu, s, 2);
                if (tq == 0 && gvalid)
                    Cf[(size_t)m * ldc + gcol] = s * p1[m];
            }
    } else {  // MODE 4: tile = (y = by>>1, part = by&1); contract 128 cols with zv
        const int part = blockIdx.y & 1;
        const int y = blockIdx.y >> 1;
        float* Cf = (float*)Cout;
#pragma unroll
        for (int mt = 0; mt < MT; mt++)
#pragma unroll
            for (int h = 0; h < 2; h++) {
                int rl = wm * (MT * 16) + mt * 16 + gq + h * 8;
                int m = m0 + rl;
                float s = 0.f;
#pragma unroll
                for (int nt = 0; nt < 4; nt++)
#pragma unroll
                    for (int p = 0; p < 2; p++) {
                        int cl = wn * 32 + nt * 8 + tq * 2 + p;
                        s += (acc[mt][nt][h * 2 + p] + sbias[cl])
                             * p0[(size_t)m * 256 + part * 128 + cl];
                    }
                s += __shfl_xor_sync(0xffffffffu, s, 1);
                s += __shfl_xor_sync(0xffffffffu, s, 2);
                if (tq == 0)
                    red[rl * 4 + wn] = s;
            }
        __syncthreads();
        if (tid < MTILE) {
            float s = red[tid * 4] + red[tid * 4 + 1]
                    + red[tid * 4 + 2] + red[tid * 4 + 3];
            Cf[(size_t)part * (BATCH * NY) + (size_t)(m0 + tid) * ldc + y] = s;
        }
    }
}

// z_next = exp(-softplus(a) + i*omega) * z + zincr   (zincr = [re | im] cols)
__global__ void znext_kernel(const float* __restrict__ zt, float* __restrict__ out)
{
    int idx = blockIdx.x * blockDim.x + threadIdx.x;
    if (idx >= BATCH * CD) return;
    int m = idx >> 7, c = idx & 127;
    float a = g_ao[m * 256 + c];
    float w = g_ao[m * 256 + 128 + c];
    float ea = 1.f / (1.f + expf(a));
    float lr = ea * cosf(w);
    float li = ea * sinf(w);
    float zr = zt[m * 256 + c];
    float zi = zt[m * 256 + 128 + c];
    out[m * 256 + c]       = lr * zr - li * zi + g_zincr[m * 256 + c];
    out[m * 256 + 128 + c] = lr * zi + li * zr + g_zincr[m * 256 + 128 + c];
}

__global__ void yt_combine_kernel(float* __restrict__ out)
{
    int idx = blockIdx.x * blockDim.x + threadIdx.x;
    if (idx >= BATCH * NY) return;
    out[BATCH * LATENT + idx] = g_ytc[idx] - g_ytc[BATCH * NY + idx] + g_ytd[idx];
}

// ================================================================================
extern "C" void kernel_launch(void* const* d_in, const int* in_sizes, int n_in,
                              void* d_out, int out_size)
{
    const float* zt      = (const float*)d_in[0];
    const float* dt      = (const float*)d_in[1];
    const float* ut      = (const float*)d_in[2];
    const float* sel_w0  = (const float*)d_in[3];
    const float* sel_b0  = (const float*)d_in[4];
    const float* sel_g0  = (const float*)d_in[5];
    const float* sel_be0 = (const float*)d_in[6];
    const float* sel_w1  = (const float*)d_in[7];
    const float* sel_b1  = (const float*)d_in[8];
    const float* sel_g1  = (const float*)d_in[9];
    const float* sel_be1 = (const float*)d_in[10];
    const float* sel_w2  = (const float*)d_in[11];
    const float* sel_b2  = (const float*)d_in[12];
    const float* alpha_w = (const float*)d_in[13];
    const float* alpha_b = (const float*)d_in[14];
    const float* omega_w = (const float*)d_in[15];
    const float* omega_b = (const float*)d_in[16];
    const float* btr_w   = (const float*)d_in[17];
    const float* btr_b   = (const float*)d_in[18];
    const float* bti_w   = (const float*)d_in[19];
    const float* bti_b   = (const float*)d_in[20];
    const float* ctr_w   = (const float*)d_in[21];
    const float* ctr_b   = (const float*)d_in[22];
    const float* cti_w   = (const float*)d_in[23];
    const float* cti_b   = (const float*)d_in[24];
    const float* dtw_w   = (const float*)d_in[25];
    const float* dtw_b   = (const float*)d_in[26];
    float* out = (float*)d_out;

    __half *A0, *W0, *W1, *W2, *Wao, *Wbt, *Wct, *Wdtw;
    __half *x1, *x2, *hz;
    float *Bao, *Bbt, *Bct, *ao, *zincr, *ytc, *ytd;
    cudaGetSymbolAddress((void**)&A0,   g_A0);
    cudaGetSymbolAddress((void**)&W0,   g_W0);
    cudaGetSymbolAddress((void**)&W1,   g_W1);
    cudaGetSymbolAddress((void**)&W2,   g_W2);
    cudaGetSymbolAddress((void**)&Wao,  g_Wao);
    cudaGetSymbolAddress((void**)&Bao,  g_Bao);
    cudaGetSymbolAddress((void**)&Wbt,  g_Wbt);
    cudaGetSymbolAddress((void**)&Bbt,  g_Bbt);
    cudaGetSymbolAddress((void**)&Wct,  g_Wct);
    cudaGetSymbolAddress((void**)&Bct,  g_Bct);
    cudaGetSymbolAddress((void**)&Wdtw, g_Wdtw);
    cudaGetSymbolAddress((void**)&x1,  g_x1);
    cudaGetSymbolAddress((void**)&x2,  g_x2);
    cudaGetSymbolAddress((void**)&hz,  g_hz);
    cudaGetSymbolAddress((void**)&ao,  g_ao);
    cudaGetSymbolAddress((void**)&zincr, g_zincr);
    cudaGetSymbolAddress((void**)&ytc, g_ytc);
    cudaGetSymbolAddress((void**)&ytd, g_ytd);

    const int SMB2 = 3 * (64  + 128) * 128 + 4096;   //  76 KB (MT=2)
    const int SMB4 = 3 * (128 + 128) * 128 + 4096;   // 100 KB (MT=4)
    cudaFuncSetAttribute((const void*)gemm_hc<1,1,2,5>, cudaFuncAttributeMaxDynamicSharedMemorySize, SMB2);
    cudaFuncSetAttribute((const void*)gemm_hc<1,1,2,4>, cudaFuncAttributeMaxDynamicSharedMemorySize, SMB2);
    cudaFuncSetAttribute((const void*)gemm_hc<2,1,2,4>, cudaFuncAttributeMaxDynamicSharedMemorySize, SMB2);
    cudaFuncSetAttribute((const void*)gemm_hc<2,0,2,4>, cudaFuncAttributeMaxDynamicSharedMemorySize, SMB2);
    cudaFuncSetAttribute((const void*)gemm_hc<3,0,4,4>, cudaFuncAttributeMaxDynamicSharedMemorySize, SMB4);
    cudaFuncSetAttribute((const void*)gemm_hc<4,0,4,4>, cudaFuncAttributeMaxDynamicSharedMemorySize, SMB4);
    cudaFuncSetAttribute((const void*)gemm_hc<5,0,4,4>, cudaFuncAttributeMaxDynamicSharedMemorySize, SMB4);

    dim3 thr(NTH);

    prep_kernel<<<2048, 256>>>(zt, dt, ut, sel_w0, sel_w1, sel_w2,
                               alpha_w, alpha_b, omega_w, omega_b,
                               btr_w, btr_b, bti_w, bti_b,
                               ctr_w, ctr_b, cti_w, cti_b, dtw_w);

    // selector MLP — MT=2 tiles (64x128)
    gemm_hc<1,1,2,5><<<dim3(128, 2), thr, SMB2>>>(A0, W0, 256, sel_b0,
                                                  nullptr, nullptr, sel_g0, sel_be0, x1, 256);
    gemm_hc<1,1,2,4><<<dim3(128, 2), thr, SMB2>>>(x1, W1, 256, sel_b1,
                                                  nullptr, nullptr, sel_g1, sel_be1, x2, 256);
    gemm_hc<2,1,2,4><<<dim3(128, 2), thr, SMB2>>>(x2, W2, 256, sel_b2,
                                                  nullptr, nullptr, nullptr, nullptr, hz, 256);
    // alpha|omega (float out for znext)
    gemm_hc<2,0,2,4><<<dim3(128, 2), thr, SMB2>>>(hz, Wao, 256, Bao,
                                                  nullptr, nullptr, nullptr, nullptr, ao, 256);
    // Bt merged (real|imag) fused with einsum('bcu,bu->bc') — one launch, MT=4
    gemm_hc<3,0,4,4><<<dim3(64, 64), thr, SMB4>>>(hz, Wbt, 8192, Bbt,
                                                  ut, dt, nullptr, nullptr, zincr, 256);
    znext_kernel<<<(BATCH * CD) / 256, 256>>>(zt, out);
    // Ct merged (real|imag interleaved per y) fused with einsum('byc,bc->by')
    gemm_hc<4,0,4,4><<<dim3(64, 100), thr, SMB4>>>(hz, Wct, 12800, Bct,
                                                   out, nullptr, nullptr, nullptr, ytc, NY);
    // Dt fused with einsum('byu,bu->by') — MT=4
    gemm_hc<5,0,4,4><<<dim3(64, 13), thr, SMB4>>>(hz, Wdtw, 1600, dtw_b,
                                                  ut, dt, nullptr, nullptr, ytd, NY);
    yt_combine_kernel<<<(BATCH * NY + 255) / 256, 256>>>(out);
}

// round 14
// speedup vs baseline: 1.0444x; 1.0444x over previous
#include <cuda_runtime.h>
#include <cuda_fp16.h>
#include <math.h>
#include <stdint.h>

#define BATCH  8192
#define LATENT 256
#define CD     128
#define UDIM   32
#define NY     50
#define NTH    256

// ---------------- scratch (static device globals; no allocation) ----------------
__device__ __half g_A0 [BATCH * 320];
__device__ __half g_W0 [256 * 320];
__device__ __half g_W1 [256 * 256];
__device__ __half g_W2 [256 * 256];
__device__ __half g_Wao[256 * 256];
__device__ float  g_Bao[256];
__device__ __half g_Wbt[8192 * 256];     // rows 0-4095 btr, 4096-8191 bti
__device__ float  g_Bbt[8192];
__device__ __half g_Wct[12800 * 256];    // row y*256+part*128+c  <- (ctr|cti)[y*128+c]
__device__ float  g_Bct[12800];
__device__ __half g_Wdtw[1600 * 256];
__device__ __half g_x1[BATCH * LATENT];
__device__ __half g_x2[BATCH * LATENT];
__device__ __half g_hz[BATCH * LATENT];
__device__ float g_ao[BATCH * LATENT];
__device__ float g_zincr[BATCH * 256];   // cols 0-127 real incr, 128-255 imag incr
__device__ float g_ytc[2 * BATCH * NY];  // [0]=Re partial, [1]=Im-weight partial
__device__ float g_ytd[BATCH * NY];

// ---------------- PTX helpers ----------------
__device__ __forceinline__ void ldsm4(uint32_t& a0, uint32_t& a1, uint32_t& a2, uint32_t& a3,
                                      uint32_t addr) {
    asm volatile("ldmatrix.sync.aligned.m8n8.x4.shared.b16 {%0,%1,%2,%3}, [%4];"
                 : "=r"(a0), "=r"(a1), "=r"(a2), "=r"(a3) : "r"(addr));
}
__device__ __forceinline__ void mma_f16(float* c,
                                        uint32_t a0, uint32_t a1, uint32_t a2, uint32_t a3,
                                        uint32_t b0, uint32_t b1) {
    asm volatile(
        "mma.sync.aligned.m16n8k16.row.col.f32.f16.f16.f32 "
        "{%0,%1,%2,%3},{%4,%5,%6,%7},{%8,%9},{%0,%1,%2,%3};"
        : "+f"(c[0]), "+f"(c[1]), "+f"(c[2]), "+f"(c[3])
        : "r"(a0), "r"(a1), "r"(a2), "r"(a3), "r"(b0), "r"(b1));
}
__device__ __forceinline__ void cp16(uint32_t dst, const void* src, int sz) {
    asm volatile("cp.async.cg.shared.global [%0], [%1], 16, %2;"
                 :: "r"(dst), "l"(src), "r"(sz));
}

// ---------------- prep: convert all GEMM operands to fp16 ----------------
#define E_A0  (BATCH * 320)
#define E_W0  (E_A0  + 256 * 320)
#define E_W1  (E_W0  + 65536)
#define E_W2  (E_W1  + 65536)
#define E_WAO (E_W2  + 65536)
#define E_BAO (E_WAO + 256)
#define E_WBT (E_BAO + 8192 * 256)
#define E_BBT (E_WBT + 8192)
#define E_WCT (E_BBT + 12800 * 256)
#define E_BCT (E_WCT + 12800)
#define E_DTW (E_BCT + 1600 * 256)

__global__ void prep_kernel(const float* __restrict__ zt, const float* __restrict__ dt,
                            const float* __restrict__ ut,
                            const float* __restrict__ sw0, const float* __restrict__ sw1,
                            const float* __restrict__ sw2,
                            const float* __restrict__ aw, const float* __restrict__ ab,
                            const float* __restrict__ ow, const float* __restrict__ ob,
                            const float* __restrict__ btr, const float* __restrict__ btr_b,
                            const float* __restrict__ bti, const float* __restrict__ bti_b,
                            const float* __restrict__ ctr, const float* __restrict__ ctr_b,
                            const float* __restrict__ cti, const float* __restrict__ cti_b,
                            const float* __restrict__ dtw)
{
    for (int idx = blockIdx.x * blockDim.x + threadIdx.x; idx < E_DTW;
         idx += gridDim.x * blockDim.x) {
        if (idx < E_A0) {
            int m = idx / 320, c = idx % 320;
            float v = 0.f;
            if (c < 256)       v = zt[m * 256 + c];
            else if (c < 288)  v = ut[m * UDIM + (c - 256)];
            else if (c == 288) v = dt[m];
            g_A0[idx] = __float2half(v);
        } else if (idx < E_W0) {
            int j = idx - E_A0;
            int r = j / 320, c = j % 320;
            g_W0[j] = __float2half((c < 289) ? sw0[r * 289 + c] : 0.f);
        } else if (idx < E_W1) {
            int j = idx - E_W0;  g_W1[j] = __float2half(sw1[j]);
        } else if (idx < E_W2) {
            int j = idx - E_W1;  g_W2[j] = __float2half(sw2[j]);
        } else if (idx < E_WAO) {
            int j = idx - E_W2;
            g_Wao[j] = __float2half((j < 128 * 256) ? aw[j] : ow[j - 128 * 256]);
        } else if (idx < E_BAO) {
            int j = idx - E_WAO;
            g_Bao[j] = (j < 128) ? ab[j] : ob[j - 128];
        } else if (idx < E_WBT) {
            int j = idx - E_BAO;
            g_Wbt[j] = __float2half((j < 4096 * 256) ? btr[j] : bti[j - 4096 * 256]);
        } else if (idx < E_BBT) {
            int j = idx - E_WBT;
            g_Bbt[j] = (j < 4096) ? btr_b[j] : bti_b[j - 4096];
        } else if (idx < E_WCT) {
            int j = idx - E_BBT;
            int r = j >> 8, k = j & 255;
            int y = r >> 8, part = (r >> 7) & 1, c = r & 127;
            int srow = (y * 128 + c) * 256 + k;
            g_Wct[j] = __float2half(part == 0 ? ctr[srow] : cti[srow]);
        } else if (idx < E_BCT) {
            int r = idx - E_WCT;
            int y = r >> 8, part = (r >> 7) & 1, c = r & 127;
            g_Bct[r] = part == 0 ? ctr_b[y * 128 + c] : cti_b[y * 128 + c];
        } else {
            int j = idx - E_BCT; g_Wdtw[j] = __float2half(dtw[j]);
        }
    }
}

// ---------------------------------------------------------------------------
// fp16 m16n8k16 fused GEMM, 256 threads, templated M-tile (MT frags/warp).
// CTA tile (MT*32) x 128, BK=64, 3-stage cp.async, 1 sync/chunk.
// Both A and B fragments loaded via ldmatrix (B: 2 x ldsm.x4 per k16-step).
// 8 warps as 2(m) x 4(n); warp tile (MT*16) x 32.   [R11 mainloop, unchanged]
//   MODE 1: BN(eval)+ReLU -> half out, ldc=256
//   MODE 2: +bias -> half out (OUTH=1) or float out (OUTH=0), ldc=256
//   MODE 3: +bias, contract 32-col u-group/warp with ut*dt, ldc by caller
//   MODE 4: +bias, contract tile's 128 cols with zv[part] (y=by>>1), out ytc
//   MODE 5: MODE 3 with group bounds (Dt), ldc=NY
// ---------------------------------------------------------------------------
template <int MODE, int OUTH, int MT>
__global__ __launch_bounds__(NTH, 2)
void gemm_hc(const __half* __restrict__ A, int K,
             const __half* __restrict__ W, int N,
             const float* __restrict__ bias,
             const float* __restrict__ p0,   // ut (3/5) | zv base (4)
             const float* __restrict__ p1,   // dt (3/5)
             const float* __restrict__ p2,   // bn gamma (1)
             const float* __restrict__ p3,   // bn beta  (1)
             void* __restrict__ Cout, int ldc)
{
    constexpr int MTILE = MT * 32;                 // 64 or 128
    constexpr int STAGE_BYTES = (MTILE + 128) * 128;
    constexpr int STGW = STAGE_BYTES / 4;
    constexpr int CTRLW = 3 * STGW;

    extern __shared__ float sm[];
    float* sbias = sm + CTRLW;
    float* sg    = sbias + 128;
    float* sbe   = sg + 128;
    float* red   = sbe + 128;                      // MTILE*4 floats (MODE 4)

    const int tid  = threadIdx.x;
    const int lane = tid & 31;
    const int warp = tid >> 5;
    const int m0 = blockIdx.x * MTILE;
    const int n0 = blockIdx.y * 128;
    const int wm = warp >> 2;           // 0..1  (MTILE/2 rows each)
    const int wn = warp & 3;            // 0..3  (32 cols each)
    const int gq = lane >> 2;
    const int tq = lane & 3;
    const uint32_t smu = (uint32_t)__cvta_generic_to_shared(sm);

    if (tid < 128) {
        int n = n0 + tid;
        sbias[tid] = (n < N) ? bias[n] : 0.f;
        if (MODE == 1) {
            sg[tid]  = p2[n] * rsqrtf(1.f + 1e-5f);
            sbe[tid] = p3[n];
        }
    }

    float acc[MT][4][4];
#pragma unroll
    for (int i = 0; i < MT; i++)
#pragma unroll
        for (int j = 0; j < 4; j++)
#pragma unroll
            for (int r = 0; r < 4; r++) acc[i][j][r] = 0.f;

    // A ldmatrix lane constants
    const int row_off = lane & 15;
    const int hi = lane >> 4;
    uint32_t abyte[MT]; int arx[MT];
#pragma unroll
    for (int mt = 0; mt < MT; mt++) {
        int r = wm * (MT * 16) + mt * 16 + row_off;
        abyte[mt] = smu + (uint32_t)(r * 128);
        arx[mt] = r & 7;
    }
    // B ldmatrix lane constants: ldsm.x4 call1 covers (nt=0,1), call2 (nt=2,3).
    const int brx = lane & 7;
    const int gpx = (lane >> 3) & 1;
    const uint32_t bb1 = smu + (uint32_t)((MTILE + wn * 32 + (lane >> 4) * 8 + brx) * 128);
    const uint32_t bb2 = bb1 + 16 * 128;

    auto issue = [&](int kc, int s) {
        const int tot = (MTILE + 128) * 8;
#pragma unroll
        for (int i = tid; i < tot; i += NTH) {
            int r = i >> 3, g16 = i & 7;
            uint32_t dst; const __half* src; int sz = 16;
            if (r < MTILE) {
                dst = smu + (uint32_t)(s * STAGE_BYTES + r * 128 + ((g16 ^ (r & 7)) << 4));
                src = A + (size_t)(m0 + r) * K + kc * 64 + g16 * 8;
            } else {
                int rb = r - MTILE;
                dst = smu + (uint32_t)(s * STAGE_BYTES + MTILE * 128 + rb * 128 + ((g16 ^ (rb & 7)) << 4));
                int n = n0 + rb;
                if (n < N) src = W + (size_t)n * K + kc * 64 + g16 * 8;
                else { src = W; sz = 0; }
            }
            cp16(dst, src, sz);
        }
        asm volatile("cp.async.commit_group;" ::: "memory");
    };

    auto compute = [&](int s) {
        const uint32_t sa = (uint32_t)(s * STAGE_BYTES);
#pragma unroll
        for (int ks = 0; ks < 4; ks++) {           // 4 x k16 per 64-k chunk
            uint32_t bf0[4], bf1[4];
            const uint32_t gx = (uint32_t)(((2 * ks + gpx) ^ brx) << 4);
            ldsm4(bf0[0], bf1[0], bf0[1], bf1[1], bb1 + sa + gx);
            ldsm4(bf0[2], bf1[2], bf0[3], bf1[3], bb2 + sa + gx);
            const int ga = 2 * ks + hi;
#pragma unroll
            for (int mt = 0; mt < MT; mt++) {
                uint32_t a0, a1, a2, a3;
                ldsm4(a0, a1, a2, a3, abyte[mt] + sa + (uint32_t)((ga ^ arx[mt]) << 4));
#pragma unroll
                for (int nt = 0; nt < 4; nt++)
                    mma_f16(acc[mt][nt], a0, a1, a2, a3, bf0[nt], bf1[nt]);
            }
        }
    };

    const int NC = K >> 6;                         // 64 k per chunk
    issue(0, 0);
    issue(1, 1);
    for (int kc = 0; kc < NC; kc++) {
        asm volatile("cp.async.wait_group 1;" ::: "memory");
        __syncthreads();
        int pf = kc + 2;
        if (pf < NC) issue(pf, pf % 3);
        else asm volatile("cp.async.commit_group;" ::: "memory");
        compute(kc % 3);
    }

    // ---------------- epilogues ----------------
    // acc r=h*2+p -> m = m0+wm*(MT*16)+mt*16+gq+h*8 ; col nl = wn*32+nt*8+tq*2+p
    if (MODE <= 2) {
#pragma unroll
        for (int nt = 0; nt < 4; nt++)
#pragma unroll
            for (int p = 0; p < 2; p++) {
                int nl = wn * 32 + nt * 8 + tq * 2 + p;
                int n = n0 + nl;
                float bi = sbias[nl];
                float gg = (MODE == 1) ? sg[nl] : 0.f;
                float bb = (MODE == 1) ? sbe[nl] : 0.f;
#pragma unroll
                for (int mt = 0; mt < MT; mt++)
#pragma unroll
                    for (int h = 0; h < 2; h++) {
                        int m = m0 + wm * (MT * 16) + mt * 16 + gq + h * 8;
                        float v = acc[mt][nt][h * 2 + p] + bi;
                        if (MODE == 1) v = fmaxf(v * gg + bb, 0.f);
                        if (OUTH) ((__half*)Cout)[(size_t)m * ldc + n] = __float2half(v);
                        else      ((float*)Cout)[(size_t)m * ldc + n] = v;
                    }
            }
    } else if (MODE == 3 || MODE == 5) {
        const int gcol = blockIdx.y * 4 + wn;
        const bool gvalid = (MODE == 3) || (gcol < NY);
        float* Cf = (float*)Cout;
#pragma unroll
        for (int mt = 0; mt < MT; mt++)
#pragma unroll
            for (int h = 0; h < 2; h++) {
                int m = m0 + wm * (MT * 16) + mt * 16 + gq + h * 8;
                float s = 0.f;
#pragma unroll
                for (int nt = 0; nt < 4; nt++)
#pragma unroll
                    for (int p = 0; p < 2; p++) {
                        int u = nt * 8 + tq * 2 + p;
                        s += (acc[mt][nt][h * 2 + p] + sbias[wn * 32 + u])
                             * p0[(size_t)m * UDIM + u];
                    }
                s += __shfl_xor_sync(0xffffffffu, s, 1);
                s += __shfl_xor_sync(0xffffffffu, s, 2);
                if (tq == 0 && gvalid)
                    Cf[(size_t)m * ldc + gcol] = s * p1[m];
            }
    } else {  // MODE 4: tile = (y = by>>1, part = by&1); contract 128 cols with zv
        const int part = blockIdx.y & 1;
        const int y = blockIdx.y >> 1;
        float* Cf = (float*)Cout;
#pragma unroll
        for (int mt = 0; mt < MT; mt++)
#pragma unroll
            for (int h = 0; h < 2; h++) {
                int rl = wm * (MT * 16) + mt * 16 + gq + h * 8;
                int m = m0 + rl;
                float s = 0.f;
#pragma unroll
                for (int nt = 0; nt < 4; nt++)
#pragma unroll
                    for (int p = 0; p < 2; p++) {
                        int cl = wn * 32 + nt * 8 + tq * 2 + p;
                        s += (acc[mt][nt][h * 2 + p] + sbias[cl])
                             * p0[(size_t)m * 256 + part * 128 + cl];
                    }
                s += __shfl_xor_sync(0xffffffffu, s, 1);
                s += __shfl_xor_sync(0xffffffffu, s, 2);
                if (tq == 0)
                    red[rl * 4 + wn] = s;
            }
        __syncthreads();
        if (tid < MTILE) {
            float s = red[tid * 4] + red[tid * 4 + 1]
                    + red[tid * 4 + 2] + red[tid * 4 + 3];
            Cf[(size_t)part * (BATCH * NY) + (size_t)(m0 + tid) * ldc + y] = s;
        }
    }
}

// z_next = exp(-softplus(a) + i*omega) * z + zincr   (zincr = [re | im] cols)
__global__ void znext_kernel(const float* __restrict__ zt, float* __restrict__ out)
{
    int idx = blockIdx.x * blockDim.x + threadIdx.x;
    if (idx >= BATCH * CD) return;
    int m = idx >> 7, c = idx & 127;
    float a = g_ao[m * 256 + c];
    float w = g_ao[m * 256 + 128 + c];
    float ea = 1.f / (1.f + expf(a));
    float lr = ea * cosf(w);
    float li = ea * sinf(w);
    float zr = zt[m * 256 + c];
    float zi = zt[m * 256 + 128 + c];
    out[m * 256 + c]       = lr * zr - li * zi + g_zincr[m * 256 + c];
    out[m * 256 + 128 + c] = lr * zi + li * zr + g_zincr[m * 256 + 128 + c];
}

__global__ void yt_combine_kernel(float* __restrict__ out)
{
    int idx = blockIdx.x * blockDim.x + threadIdx.x;
    if (idx >= BATCH * NY) return;
    out[BATCH * LATENT + idx] = g_ytc[idx] - g_ytc[BATCH * NY + idx] + g_ytd[idx];
}

// ================================================================================
extern "C" void kernel_launch(void* const* d_in, const int* in_sizes, int n_in,
                              void* d_out, int out_size)
{
    const float* zt      = (const float*)d_in[0];
    const float* dt      = (const float*)d_in[1];
    const float* ut      = (const float*)d_in[2];
    const float* sel_w0  = (const float*)d_in[3];
    const float* sel_b0  = (const float*)d_in[4];
    const float* sel_g0  = (const float*)d_in[5];
    const float* sel_be0 = (const float*)d_in[6];
    const float* sel_w1  = (const float*)d_in[7];
    const float* sel_b1  = (const float*)d_in[8];
    const float* sel_g1  = (const float*)d_in[9];
    const float* sel_be1 = (const float*)d_in[10];
    const float* sel_w2  = (const float*)d_in[11];
    const float* sel_b2  = (const float*)d_in[12];
    const float* alpha_w = (const float*)d_in[13];
    const float* alpha_b = (const float*)d_in[14];
    const float* omega_w = (const float*)d_in[15];
    const float* omega_b = (const float*)d_in[16];
    const float* btr_w   = (const float*)d_in[17];
    const float* btr_b   = (const float*)d_in[18];
    const float* bti_w   = (const float*)d_in[19];
    const float* bti_b   = (const float*)d_in[20];
    const float* ctr_w   = (const float*)d_in[21];
    const float* ctr_b   = (const float*)d_in[22];
    const float* cti_w   = (const float*)d_in[23];
    const float* cti_b   = (const float*)d_in[24];
    const float* dtw_w   = (const float*)d_in[25];
    const float* dtw_b   = (const float*)d_in[26];
    float* out = (float*)d_out;

    __half *A0, *W0, *W1, *W2, *Wao, *Wbt, *Wct, *Wdtw;
    __half *x1, *x2, *hz;
    float *Bao, *Bbt, *Bct, *ao, *zincr, *ytc, *ytd;
    cudaGetSymbolAddress((void**)&A0,   g_A0);
    cudaGetSymbolAddress((void**)&W0,   g_W0);
    cudaGetSymbolAddress((void**)&W1,   g_W1);
    cudaGetSymbolAddress((void**)&W2,   g_W2);
    cudaGetSymbolAddress((void**)&Wao,  g_Wao);
    cudaGetSymbolAddress((void**)&Bao,  g_Bao);
    cudaGetSymbolAddress((void**)&Wbt,  g_Wbt);
    cudaGetSymbolAddress((void**)&Bbt,  g_Bbt);
    cudaGetSymbolAddress((void**)&Wct,  g_Wct);
    cudaGetSymbolAddress((void**)&Bct,  g_Bct);
    cudaGetSymbolAddress((void**)&Wdtw, g_Wdtw);
    cudaGetSymbolAddress((void**)&x1,  g_x1);
    cudaGetSymbolAddress((void**)&x2,  g_x2);
    cudaGetSymbolAddress((void**)&hz,  g_hz);
    cudaGetSymbolAddress((void**)&ao,  g_ao);
    cudaGetSymbolAddress((void**)&zincr, g_zincr);
    cudaGetSymbolAddress((void**)&ytc, g_ytc);
    cudaGetSymbolAddress((void**)&ytd, g_ytd);

    const int SMB2 = 3 * (64  + 128) * 128 + 4096;   //  76 KB (MT=2)
    const int SMB4 = 3 * (128 + 128) * 128 + 4096;   // 100 KB (MT=4)
    cudaFuncSetAttribute((const void*)gemm_hc<1,1,2>, cudaFuncAttributeMaxDynamicSharedMemorySize, SMB2);
    cudaFuncSetAttribute((const void*)gemm_hc<2,1,2>, cudaFuncAttributeMaxDynamicSharedMemorySize, SMB2);
    cudaFuncSetAttribute((const void*)gemm_hc<2,0,2>, cudaFuncAttributeMaxDynamicSharedMemorySize, SMB2);
    cudaFuncSetAttribute((const void*)gemm_hc<3,0,4>, cudaFuncAttributeMaxDynamicSharedMemorySize, SMB4);
    cudaFuncSetAttribute((const void*)gemm_hc<4,0,4>, cudaFuncAttributeMaxDynamicSharedMemorySize, SMB4);
    cudaFuncSetAttribute((const void*)gemm_hc<5,0,4>, cudaFuncAttributeMaxDynamicSharedMemorySize, SMB4);

    dim3 thr(NTH);

    prep_kernel<<<2048, 256>>>(zt, dt, ut, sel_w0, sel_w1, sel_w2,
                               alpha_w, alpha_b, omega_w, omega_b,
                               btr_w, btr_b, bti_w, bti_b,
                               ctr_w, ctr_b, cti_w, cti_b, dtw_w);

    // selector MLP — MT=2 tiles (64x128)
    gemm_hc<1,1,2><<<dim3(128, 2), thr, SMB2>>>(A0, 320, W0, 256, sel_b0,
                                                nullptr, nullptr, sel_g0, sel_be0, x1, 256);
    gemm_hc<1,1,2><<<dim3(128, 2), thr, SMB2>>>(x1, 256, W1, 256, sel_b1,
                                                nullptr, nullptr, sel_g1, sel_be1, x2, 256);
    gemm_hc<2,1,2><<<dim3(128, 2), thr, SMB2>>>(x2, 256, W2, 256, sel_b2,
                                                nullptr, nullptr, nullptr, nullptr, hz, 256);
    // alpha|omega (float out for znext)
    gemm_hc<2,0,2><<<dim3(128, 2), thr, SMB2>>>(hz, 256, Wao, 256, Bao,
                                                nullptr, nullptr, nullptr, nullptr, ao, 256);
    // Bt merged (real|imag) fused with einsum('bcu,bu->bc') — one launch, MT=4
    gemm_hc<3,0,4><<<dim3(64, 64), thr, SMB4>>>(hz, 256, Wbt, 8192, Bbt,
                                                ut, dt, nullptr, nullptr, zincr, 256);
    znext_kernel<<<(BATCH * CD) / 256, 256>>>(zt, out);
    // Ct merged (real|imag interleaved per y) fused with einsum('byc,bc->by')
    gemm_hc<4,0,4><<<dim3(64, 100), thr, SMB4>>>(hz, 256, Wct, 12800, Bct,
                                                 out, nullptr, nullptr, nullptr, ytc, NY);
    // Dt fused with einsum('byu,bu->by') — MT=4
    gemm_hc<5,0,4><<<dim3(64, 13), thr, SMB4>>>(hz, 256, Wdtw, 1600, dtw_b,
                                                ut, dt, nullptr, nullptr, ytd, NY);
    yt_combine_kernel<<<(BATCH * NY + 255) / 256, 256>>>(out);
}

// round 16
// speedup vs baseline: 1.0900x; 1.0437x over previous
#include <cuda_runtime.h>
#include <cuda_fp16.h>
#include <math.h>
#include <stdint.h>

#define BATCH  8192
#define LATENT 256
#define CD     128
#define UDIM   32
#define NY     50
#define NTH    256

// ---------------- scratch (static device globals; no allocation) ----------------
__device__ __half g_A0 [BATCH * 320];
__device__ __half g_W0 [256 * 320];
__device__ __half g_W1 [256 * 256];
__device__ __half g_W2 [256 * 256];
__device__ __half g_Wao[256 * 256];
__device__ float  g_Bao[256];
__device__ __half g_Wbt[8192 * 256];     // rows 0-4095 btr, 4096-8191 bti
__device__ float  g_Bbt[8192];
__device__ __half g_Wct[12800 * 256];    // row y*256+part*128+c  <- (ctr|cti)[y*128+c]
__device__ float  g_Bct[12800];
__device__ __half g_Wdtw[1600 * 256];
__device__ __half g_x1[BATCH * LATENT];
__device__ __half g_x2[BATCH * LATENT];
__device__ __half g_hz[BATCH * LATENT];
__device__ float g_ao[BATCH * LATENT];
__device__ float g_zincr[BATCH * 256];   // cols 0-127 real incr, 128-255 imag incr
__device__ float g_ytc[2 * BATCH * NY];  // [0]=Re partial, [1]=Im-weight partial
__device__ float g_ytd[BATCH * NY];

// ---------------- PTX helpers ----------------
__device__ __forceinline__ void ldsm4(uint32_t& a0, uint32_t& a1, uint32_t& a2, uint32_t& a3,
                                      uint32_t addr) {
    asm volatile("ldmatrix.sync.aligned.m8n8.x4.shared.b16 {%0,%1,%2,%3}, [%4];"
                 : "=r"(a0), "=r"(a1), "=r"(a2), "=r"(a3) : "r"(addr));
}
__device__ __forceinline__ void mma_f16(float* c,
                                        uint32_t a0, uint32_t a1, uint32_t a2, uint32_t a3,
                                        uint32_t b0, uint32_t b1) {
    asm volatile(
        "mma.sync.aligned.m16n8k16.row.col.f32.f16.f16.f32 "
        "{%0,%1,%2,%3},{%4,%5,%6,%7},{%8,%9},{%0,%1,%2,%3};"
        : "+f"(c[0]), "+f"(c[1]), "+f"(c[2]), "+f"(c[3])
        : "r"(a0), "r"(a1), "r"(a2), "r"(a3), "r"(b0), "r"(b1));
}
__device__ __forceinline__ void cp16(uint32_t dst, const void* src, int sz) {
    asm volatile("cp.async.cg.shared.global [%0], [%1], 16, %2;"
                 :: "r"(dst), "l"(src), "r"(sz));
}

// ---------------- prep: convert all GEMM operands to fp16 ----------------
#define E_A0  (BATCH * 320)
#define E_W0  (E_A0  + 256 * 320)
#define E_W1  (E_W0  + 65536)
#define E_W2  (E_W1  + 65536)
#define E_WAO (E_W2  + 65536)
#define E_BAO (E_WAO + 256)
#define E_WBT (E_BAO + 8192 * 256)
#define E_BBT (E_WBT + 8192)
#define E_WCT (E_BBT + 12800 * 256)
#define E_BCT (E_WCT + 12800)
#define E_DTW (E_BCT + 1600 * 256)

__global__ void prep_kernel(const float* __restrict__ zt, const float* __restrict__ dt,
                            const float* __restrict__ ut,
                            const float* __restrict__ sw0, const float* __restrict__ sw1,
                            const float* __restrict__ sw2,
                            const float* __restrict__ aw, const float* __restrict__ ab,
                            const float* __restrict__ ow, const float* __restrict__ ob,
                            const float* __restrict__ btr, const float* __restrict__ btr_b,
                            const float* __restrict__ bti, const float* __restrict__ bti_b,
                            const float* __restrict__ ctr, const float* __restrict__ ctr_b,
                            const float* __restrict__ cti, const float* __restrict__ cti_b,
                            const float* __restrict__ dtw)
{
    for (int idx = blockIdx.x * blockDim.x + threadIdx.x; idx < E_DTW;
         idx += gridDim.x * blockDim.x) {
        if (idx < E_A0) {
            int m = idx / 320, c = idx % 320;
            float v = 0.f;
            if (c < 256)       v = zt[m * 256 + c];
            else if (c < 288)  v = ut[m * UDIM + (c - 256)];
            else if (c == 288) v = dt[m];
            g_A0[idx] = __float2half(v);
        } else if (idx < E_W0) {
            int j = idx - E_A0;
            int r = j / 320, c = j % 320;
            g_W0[j] = __float2half((c < 289) ? sw0[r * 289 + c] : 0.f);
        } else if (idx < E_W1) {
            int j = idx - E_W0;  g_W1[j] = __float2half(sw1[j]);
        } else if (idx < E_W2) {
            int j = idx - E_W1;  g_W2[j] = __float2half(sw2[j]);
        } else if (idx < E_WAO) {
            int j = idx - E_W2;
            g_Wao[j] = __float2half((j < 128 * 256) ? aw[j] : ow[j - 128 * 256]);
        } else if (idx < E_BAO) {
            int j = idx - E_WAO;
            g_Bao[j] = (j < 128) ? ab[j] : ob[j - 128];
        } else if (idx < E_WBT) {
            int j = idx - E_BAO;
            g_Wbt[j] = __float2half((j < 4096 * 256) ? btr[j] : bti[j - 4096 * 256]);
        } else if (idx < E_BBT) {
            int j = idx - E_WBT;
            g_Bbt[j] = (j < 4096) ? btr_b[j] : bti_b[j - 4096];
        } else if (idx < E_WCT) {
            int j = idx - E_BBT;
            int r = j >> 8, k = j & 255;
            int y = r >> 8, part = (r >> 7) & 1, c = r & 127;
            int srow = (y * 128 + c) * 256 + k;
            g_Wct[j] = __float2half(part == 0 ? ctr[srow] : cti[srow]);
        } else if (idx < E_BCT) {
            int r = idx - E_WCT;
            int y = r >> 8, part = (r >> 7) & 1, c = r & 127;
            g_Bct[r] = part == 0 ? ctr_b[y * 128 + c] : cti_b[y * 128 + c];
        } else {
            int j = idx - E_BCT; g_Wdtw[j] = __float2half(dtw[j]);
        }
    }
}

// ---------------------------------------------------------------------------
// fp16 m16n8k16 fused GEMM, 256 threads. Templated M-tile (MT), N-tiles/CTA (T).
// CTA processes T consecutive 128-col tiles as ONE flat cp.async pipeline
// (global chunk q -> tile q/NCK, k-chunk q%NCK); acc flushed per tile.
// Inner issue/compute identical to R14. 8 warps 2(m) x 4(n), warp (MT*16) x 32.
//   MODE 1: BN(eval)+ReLU -> half out (T=1), ldc=256
//   MODE 2: +bias -> half (OUTH=1) / float (OUTH=0) out (T=1), ldc=256
//   MODE 3: +bias, contract 32-col u-group/warp with ut*dt, gcol = gy*4+wn
//   MODE 4: +bias, contract 128 cols with zv[part] (gy -> y=gy>>1, part=gy&1)
//   MODE 5: MODE 3 with gcol < NY bounds (Dt)
// ---------------------------------------------------------------------------
template <int MODE, int OUTH, int MT, int T>
__global__ __launch_bounds__(NTH, 2)
void gemm_hc(const __half* __restrict__ A, int K,
             const __half* __restrict__ W, int N,
             const float* __restrict__ bias,
             const float* __restrict__ p0,   // ut (3/5) | zv base (4)
             const float* __restrict__ p1,   // dt (3/5)
             const float* __restrict__ p2,   // bn gamma (1)
             const float* __restrict__ p3,   // bn beta  (1)
             void* __restrict__ Cout, int ldc)
{
    constexpr int MTILE = MT * 32;                 // 64 or 128
    constexpr int STAGE_BYTES = (MTILE + 128) * 128;
    constexpr int STGW = STAGE_BYTES / 4;
    constexpr int CTRLW = 3 * STGW;

    extern __shared__ float sm[];
    float* sbias = sm + CTRLW;
    float* sg    = sbias + 128;
    float* sbe   = sg + 128;
    float* red   = sbe + 128;                      // MTILE*4 floats (MODE 4)

    const int tid  = threadIdx.x;
    const int lane = tid & 31;
    const int warp = tid >> 5;
    const int m0 = blockIdx.x * MTILE;
    const int wm = warp >> 2;           // 0..1  (MTILE/2 rows each)
    const int wn = warp & 3;            // 0..3  (32 cols each)
    const int gq = lane >> 2;
    const int tq = lane & 3;
    const uint32_t smu = (uint32_t)__cvta_generic_to_shared(sm);

    if (MODE <= 1 || MODE == 2) {
        if (tid < 128) {
            int n = blockIdx.y * 128 + tid;
            sbias[tid] = (n < N) ? bias[n] : 0.f;
            if (MODE == 1) {
                sg[tid]  = p2[n] * rsqrtf(1.f + 1e-5f);
                sbe[tid] = p3[n];
            }
        }
    }

    float acc[MT][4][4];
#pragma unroll
    for (int i = 0; i < MT; i++)
#pragma unroll
        for (int j = 0; j < 4; j++)
#pragma unroll
            for (int r = 0; r < 4; r++) acc[i][j][r] = 0.f;

    // A ldmatrix lane constants
    const int row_off = lane & 15;
    const int hi = lane >> 4;
    uint32_t abyte[MT]; int arx[MT];
#pragma unroll
    for (int mt = 0; mt < MT; mt++) {
        int r = wm * (MT * 16) + mt * 16 + row_off;
        abyte[mt] = smu + (uint32_t)(r * 128);
        arx[mt] = r & 7;
    }
    // B ldmatrix lane constants
    const int brx = lane & 7;
    const int gpx = (lane >> 3) & 1;
    const uint32_t bb1 = smu + (uint32_t)((MTILE + wn * 32 + (lane >> 4) * 8 + brx) * 128);
    const uint32_t bb2 = bb1 + 16 * 128;

    const int NCK = K >> 6;             // 64-k chunks per tile
    const int QT = T * NCK;             // total chunks in flat pipeline

    auto issue = [&](int q, int s) {
        const int kc = (T == 1) ? q : (q % NCK);
        const int n0q = ((T == 1) ? blockIdx.y : (blockIdx.y * T + q / NCK)) * 128;
        const int tot = (MTILE + 128) * 8;
#pragma unroll
        for (int i = tid; i < tot; i += NTH) {
            int r = i >> 3, g16 = i & 7;
            uint32_t dst; const __half* src; int sz = 16;
            if (r < MTILE) {
                dst = smu + (uint32_t)(s * STAGE_BYTES + r * 128 + ((g16 ^ (r & 7)) << 4));
                src = A + (size_t)(m0 + r) * K + kc * 64 + g16 * 8;
            } else {
                int rb = r - MTILE;
                dst = smu + (uint32_t)(s * STAGE_BYTES + MTILE * 128 + rb * 128 + ((g16 ^ (rb & 7)) << 4));
                int n = n0q + rb;
                if (n < N) src = W + (size_t)n * K + kc * 64 + g16 * 8;
                else { src = W; sz = 0; }
            }
            cp16(dst, src, sz);
        }
        asm volatile("cp.async.commit_group;" ::: "memory");
    };

    auto compute = [&](int s) {
        const uint32_t sa = (uint32_t)(s * STAGE_BYTES);
#pragma unroll
        for (int ks = 0; ks < 4; ks++) {           // 4 x k16 per 64-k chunk
            uint32_t bf0[4], bf1[4];
            const uint32_t gx = (uint32_t)(((2 * ks + gpx) ^ brx) << 4);
            ldsm4(bf0[0], bf1[0], bf0[1], bf1[1], bb1 + sa + gx);
            ldsm4(bf0[2], bf1[2], bf0[3], bf1[3], bb2 + sa + gx);
            const int ga = 2 * ks + hi;
#pragma unroll
            for (int mt = 0; mt < MT; mt++) {
                uint32_t a0, a1, a2, a3;
                ldsm4(a0, a1, a2, a3, abyte[mt] + sa + (uint32_t)((ga ^ arx[mt]) << 4));
#pragma unroll
                for (int nt = 0; nt < 4; nt++)
                    mma_f16(acc[mt][nt], a0, a1, a2, a3, bf0[nt], bf1[nt]);
            }
        }
    };

    // per-tile accumulator flush
    auto flush = [&](int t) {
        const int gy = (T == 1) ? blockIdx.y : (blockIdx.y * T + t);
        if (MODE <= 2) {
            const int n0 = gy * 128;
#pragma unroll
            for (int nt = 0; nt < 4; nt++)
#pragma unroll
                for (int p = 0; p < 2; p++) {
                    int nl = wn * 32 + nt * 8 + tq * 2 + p;
                    int n = n0 + nl;
                    float bi = sbias[nl];
                    float gg = (MODE == 1) ? sg[nl] : 0.f;
                    float bb = (MODE == 1) ? sbe[nl] : 0.f;
#pragma unroll
                    for (int mt = 0; mt < MT; mt++)
#pragma unroll
                        for (int h = 0; h < 2; h++) {
                            int m = m0 + wm * (MT * 16) + mt * 16 + gq + h * 8;
                            float v = acc[mt][nt][h * 2 + p] + bi;
                            if (MODE == 1) v = fmaxf(v * gg + bb, 0.f);
                            if (OUTH) ((__half*)Cout)[(size_t)m * ldc + n] = __float2half(v);
                            else      ((float*)Cout)[(size_t)m * ldc + n] = v;
                        }
                }
        } else if (MODE == 3 || MODE == 5) {
            const int gcol = gy * 4 + wn;
            const bool gvalid = (MODE == 3) || (gcol < NY);
            float* Cf = (float*)Cout;
            float bv[4][2];
#pragma unroll
            for (int nt = 0; nt < 4; nt++)
#pragma unroll
                for (int p = 0; p < 2; p++) {
                    int n = gy * 128 + wn * 32 + nt * 8 + tq * 2 + p;
                    bv[nt][p] = (n < N) ? bias[n] : 0.f;
                }
#pragma unroll
            for (int mt = 0; mt < MT; mt++)
#pragma unroll
                for (int h = 0; h < 2; h++) {
                    int m = m0 + wm * (MT * 16) + mt * 16 + gq + h * 8;
                    float s = 0.f;
#pragma unroll
                    for (int nt = 0; nt < 4; nt++)
#pragma unroll
                        for (int p = 0; p < 2; p++) {
                            int u = nt * 8 + tq * 2 + p;
                            s += (acc[mt][nt][h * 2 + p] + bv[nt][p])
                                 * p0[(size_t)m * UDIM + u];
                        }
                    s += __shfl_xor_sync(0xffffffffu, s, 1);
                    s += __shfl_xor_sync(0xffffffffu, s, 2);
                    if (tq == 0 && gvalid)
                        Cf[(size_t)m * ldc + gcol] = s * p1[m];
                }
        } else {  // MODE 4
            const int part = gy & 1;
            const int y = gy >> 1;
            float* Cf = (float*)Cout;
            float bv[4][2];
#pragma unroll
            for (int nt = 0; nt < 4; nt++)
#pragma unroll
                for (int p = 0; p < 2; p++)
                    bv[nt][p] = bias[gy * 128 + wn * 32 + nt * 8 + tq * 2 + p];
#pragma unroll
            for (int mt = 0; mt < MT; mt++)
#pragma unroll
                for (int h = 0; h < 2; h++) {
                    int rl = wm * (MT * 16) + mt * 16 + gq + h * 8;
                    int m = m0 + rl;
                    float s = 0.f;
#pragma unroll
                    for (int nt = 0; nt < 4; nt++)
#pragma unroll
                        for (int p = 0; p < 2; p++) {
                            int cl = wn * 32 + nt * 8 + tq * 2 + p;
                            s += (acc[mt][nt][h * 2 + p] + bv[nt][p])
                                 * p0[(size_t)m * 256 + part * 128 + cl];
                        }
                    s += __shfl_xor_sync(0xffffffffu, s, 1);
                    s += __shfl_xor_sync(0xffffffffu, s, 2);
                    if (tq == 0)
                        red[rl * 4 + wn] = s;
                }
            __syncthreads();
            if (tid < MTILE) {
                float s = red[tid * 4] + red[tid * 4 + 1]
                        + red[tid * 4 + 2] + red[tid * 4 + 3];
                Cf[(size_t)part * (BATCH * NY) + (size_t)(m0 + tid) * ldc + y] = s;
            }
        }
        // zero accumulators for the next tile
        if (T > 1) {
#pragma unroll
            for (int i = 0; i < MT; i++)
#pragma unroll
                for (int j = 0; j < 4; j++)
#pragma unroll
                    for (int r = 0; r < 4; r++) acc[i][j][r] = 0.f;
        }
    };

    issue(0, 0);
    issue(1, 1);
    for (int q = 0; q < QT; q++) {
        asm volatile("cp.async.wait_group 1;" ::: "memory");
        __syncthreads();
        int pf = q + 2;
        if (pf < QT) issue(pf, pf % 3);
        else asm volatile("cp.async.commit_group;" ::: "memory");
        compute(q % 3);
        if ((q + 1) % NCK == 0) flush(q / NCK);
    }
}

// z_next = exp(-softplus(a) + i*omega) * z + zincr   (zincr = [re | im] cols)
__global__ void znext_kernel(const float* __restrict__ zt, float* __restrict__ out)
{
    int idx = blockIdx.x * blockDim.x + threadIdx.x;
    if (idx >= BATCH * CD) return;
    int m = idx >> 7, c = idx & 127;
    float a = g_ao[m * 256 + c];
    float w = g_ao[m * 256 + 128 + c];
    float ea = 1.f / (1.f + expf(a));
    float lr = ea * cosf(w);
    float li = ea * sinf(w);
    float zr = zt[m * 256 + c];
    float zi = zt[m * 256 + 128 + c];
    out[m * 256 + c]       = lr * zr - li * zi + g_zincr[m * 256 + c];
    out[m * 256 + 128 + c] = lr * zi + li * zr + g_zincr[m * 256 + 128 + c];
}

__global__ void yt_combine_kernel(float* __restrict__ out)
{
    int idx = blockIdx.x * blockDim.x + threadIdx.x;
    if (idx >= BATCH * NY) return;
    out[BATCH * LATENT + idx] = g_ytc[idx] - g_ytc[BATCH * NY + idx] + g_ytd[idx];
}

// ================================================================================
extern "C" void kernel_launch(void* const* d_in, const int* in_sizes, int n_in,
                              void* d_out, int out_size)
{
    const float* zt      = (const float*)d_in[0];
    const float* dt      = (const float*)d_in[1];
    const float* ut      = (const float*)d_in[2];
    const float* sel_w0  = (const float*)d_in[3];
    const float* sel_b0  = (const float*)d_in[4];
    const float* sel_g0  = (const float*)d_in[5];
    const float* sel_be0 = (const float*)d_in[6];
    const float* sel_w1  = (const float*)d_in[7];
    const float* sel_b1  = (const float*)d_in[8];
    const float* sel_g1  = (const float*)d_in[9];
    const float* sel_be1 = (const float*)d_in[10];
    const float* sel_w2  = (const float*)d_in[11];
    const float* sel_b2  = (const float*)d_in[12];
    const float* alpha_w = (const float*)d_in[13];
    const float* alpha_b = (const float*)d_in[14];
    const float* omega_w = (const float*)d_in[15];
    const float* omega_b = (const float*)d_in[16];
    const float* btr_w   = (const float*)d_in[17];
    const float* btr_b   = (const float*)d_in[18];
    const float* bti_w   = (const float*)d_in[19];
    const float* bti_b   = (const float*)d_in[20];
    const float* ctr_w   = (const float*)d_in[21];
    const float* ctr_b   = (const float*)d_in[22];
    const float* cti_w   = (const float*)d_in[23];
    const float* cti_b   = (const float*)d_in[24];
    const float* dtw_w   = (const float*)d_in[25];
    const float* dtw_b   = (const float*)d_in[26];
    float* out = (float*)d_out;

    __half *A0, *W0, *W1, *W2, *Wao, *Wbt, *Wct, *Wdtw;
    __half *x1, *x2, *hz;
    float *Bao, *Bbt, *Bct, *ao, *zincr, *ytc, *ytd;
    cudaGetSymbolAddress((void**)&A0,   g_A0);
    cudaGetSymbolAddress((void**)&W0,   g_W0);
    cudaGetSymbolAddress((void**)&W1,   g_W1);
    cudaGetSymbolAddress((void**)&W2,   g_W2);
    cudaGetSymbolAddress((void**)&Wao,  g_Wao);
    cudaGetSymbolAddress((void**)&Bao,  g_Bao);
    cudaGetSymbolAddress((void**)&Wbt,  g_Wbt);
    cudaGetSymbolAddress((void**)&Bbt,  g_Bbt);
    cudaGetSymbolAddress((void**)&Wct,  g_Wct);
    cudaGetSymbolAddress((void**)&Bct,  g_Bct);
    cudaGetSymbolAddress((void**)&Wdtw, g_Wdtw);
    cudaGetSymbolAddress((void**)&x1,  g_x1);
    cudaGetSymbolAddress((void**)&x2,  g_x2);
    cudaGetSymbolAddress((void**)&hz,  g_hz);
    cudaGetSymbolAddress((void**)&ao,  g_ao);
    cudaGetSymbolAddress((void**)&zincr, g_zincr);
    cudaGetSymbolAddress((void**)&ytc, g_ytc);
    cudaGetSymbolAddress((void**)&ytd, g_ytd);

    const int SMB2 = 3 * (64  + 128) * 128 + 4096;   //  76 KB (MT=2)
    const int SMB4 = 3 * (128 + 128) * 128 + 4096;   // 100 KB (MT=4)
    cudaFuncSetAttribute((const void*)gemm_hc<1,1,2,1>, cudaFuncAttributeMaxDynamicSharedMemorySize, SMB2);
    cudaFuncSetAttribute((const void*)gemm_hc<2,1,2,1>, cudaFuncAttributeMaxDynamicSharedMemorySize, SMB2);
    cudaFuncSetAttribute((const void*)gemm_hc<2,0,2,1>, cudaFuncAttributeMaxDynamicSharedMemorySize, SMB2);
    cudaFuncSetAttribute((const void*)gemm_hc<3,0,4,4>, cudaFuncAttributeMaxDynamicSharedMemorySize, SMB4);
    cudaFuncSetAttribute((const void*)gemm_hc<4,0,4,4>, cudaFuncAttributeMaxDynamicSharedMemorySize, SMB4);
    cudaFuncSetAttribute((const void*)gemm_hc<5,0,4,1>, cudaFuncAttributeMaxDynamicSharedMemorySize, SMB4);

    dim3 thr(NTH);

    prep_kernel<<<2048, 256>>>(zt, dt, ut, sel_w0, sel_w1, sel_w2,
                               alpha_w, alpha_b, omega_w, omega_b,
                               btr_w, btr_b, bti_w, bti_b,
                               ctr_w, ctr_b, cti_w, cti_b, dtw_w);

    // selector MLP — MT=2 tiles (64x128)
    gemm_hc<1,1,2,1><<<dim3(128, 2), thr, SMB2>>>(A0, 320, W0, 256, sel_b0,
                                                  nullptr, nullptr, sel_g0, sel_be0, x1, 256);
    gemm_hc<1,1,2,1><<<dim3(128, 2), thr, SMB2>>>(x1, 256, W1, 256, sel_b1,
                                                  nullptr, nullptr, sel_g1, sel_be1, x2, 256);
    gemm_hc<2,1,2,1><<<dim3(128, 2), thr, SMB2>>>(x2, 256, W2, 256, sel_b2,
                                                  nullptr, nullptr, nullptr, nullptr, hz, 256);
    // alpha|omega (float out for znext)
    gemm_hc<2,0,2,1><<<dim3(128, 2), thr, SMB2>>>(hz, 256, Wao, 256, Bao,
                                                  nullptr, nullptr, nullptr, nullptr, ao, 256);
    // Bt merged (real|imag), T=4 flat pipeline
    gemm_hc<3,0,4,4><<<dim3(64, 16), thr, SMB4>>>(hz, 256, Wbt, 8192, Bbt,
                                                  ut, dt, nullptr, nullptr, zincr, 256);
    znext_kernel<<<(BATCH * CD) / 256, 256>>>(zt, out);
    // Ct merged (real|imag interleaved per y), T=4 flat pipeline
    gemm_hc<4,0,4,4><<<dim3(64, 25), thr, SMB4>>>(hz, 256, Wct, 12800, Bct,
                                                  out, nullptr, nullptr, nullptr, ytc, NY);
    // Dt, T=1
    gemm_hc<5,0,4,1><<<dim3(64, 13), thr, SMB4>>>(hz, 256, Wdtw, 1600, dtw_b,
                                                  ut, dt, nullptr, nullptr, ytd, NY);
    yt_combine_kernel<<<(BATCH * NY + 255) / 256, 256>>>(out);
}